// round 8
// baseline (speedup 1.0000x reference)
#include <cuda_runtime.h>
#include <cstdint>
#include <math.h>

#define Nb 512
#define Tt 64
#define Dd 512
#define Hh 512
#define FH 2048

// Persistent state (device globals: no allocations allowed)
__device__ float g_h[2][Nb * Hh];
__device__ float g_c[2][Nb * Hh];
__device__ float g_attn[Nb * Hh];

// ---------------------------------------------------------------------------
// init: h0 = c0 = mean over the 16 spatial positions of A
// ---------------------------------------------------------------------------
__global__ __launch_bounds__(128) void init_kernel(const float* __restrict__ A) {
    int n = blockIdx.x, tid = threadIdx.x;
    const float4* base = (const float4*)(A + (size_t)n * Hh * 16);
#pragma unroll
    for (int i = 0; i < 4; i++) {
        int r = tid + i * 128;
        float4 v0 = base[r * 4 + 0], v1 = base[r * 4 + 1];
        float4 v2 = base[r * 4 + 2], v3 = base[r * 4 + 3];
        float s = (v0.x + v0.y + v0.z + v0.w) + (v1.x + v1.y + v1.z + v1.w)
                + (v2.x + v2.y + v2.z + v2.w) + (v3.x + v3.y + v3.z + v3.w);
        float m = s * (1.0f / 16.0f);
        g_h[0][n * Hh + r] = m;
        g_c[0][n * Hh + r] = m;
    }
}

// ---------------------------------------------------------------------------
// attention v3: single wave. 128 blocks x 256 threads, 4 rows per block,
// register double-buffered so row rr+1's loads overlap row rr's
// reduce/softmax/output. A row read once into registers, reused for output.
// ---------------------------------------------------------------------------
__global__ __launch_bounds__(256) void attn_kernel(const float* __restrict__ A, int pi) {
    const int bid = blockIdx.x, tid = threadIdx.x;
    const int lane = tid & 31, warp = tid >> 5;
    const float* hsrc = g_h[pi];

    __shared__ float red[8][16];
    __shared__ float aw[16];

    float4 cur[8];
    float hcur[2];

    const int n0 = bid * 4;
    {
        const float4* base = (const float4*)(A + (size_t)n0 * Hh * 16);
#pragma unroll
        for (int i = 0; i < 2; i++) {
            int r = tid + i * 256;
#pragma unroll
            for (int q = 0; q < 4; q++) cur[i * 4 + q] = base[r * 4 + q];
            hcur[i] = hsrc[(size_t)n0 * Hh + r];
        }
    }

#pragma unroll
    for (int rr = 0; rr < 4; rr++) {
        const int n = n0 + rr;

        // kick off next row's loads before any compute on this row
        float4 nxt[8];
        float hnxt[2];
        if (rr < 3) {
            const float4* base = (const float4*)(A + (size_t)(n + 1) * Hh * 16);
#pragma unroll
            for (int i = 0; i < 2; i++) {
                int r = tid + i * 256;
#pragma unroll
                for (int q = 0; q < 4; q++) nxt[i * 4 + q] = base[r * 4 + q];
                hnxt[i] = hsrc[(size_t)(n + 1) * Hh + r];
            }
        }

        // scores partials: part[p] = sum_r h[r] * A[r][p]  (this thread's 2 rows)
        float part[16];
#pragma unroll
        for (int i = 0; i < 2; i++) {
#pragma unroll
            for (int q = 0; q < 4; q++) {
                float4 v = cur[i * 4 + q];
                if (i == 0) {
                    part[q * 4 + 0] = hcur[0] * v.x; part[q * 4 + 1] = hcur[0] * v.y;
                    part[q * 4 + 2] = hcur[0] * v.z; part[q * 4 + 3] = hcur[0] * v.w;
                } else {
                    part[q * 4 + 0] += hcur[1] * v.x; part[q * 4 + 1] += hcur[1] * v.y;
                    part[q * 4 + 2] += hcur[1] * v.z; part[q * 4 + 3] += hcur[1] * v.w;
                }
            }
        }

#pragma unroll
        for (int off = 16; off >= 1; off >>= 1)
#pragma unroll
            for (int p = 0; p < 16; p++)
                part[p] += __shfl_xor_sync(0xffffffffu, part[p], off);

        if (lane == 0) {
#pragma unroll
            for (int p = 0; p < 16; p++) red[warp][p] = part[p];
        }
        __syncthreads();

        if (warp == 0) {
            // lanes 0-15 own p=lane; lanes 16-31 mirror (full-warp shfl)
            int p = lane & 15;
            const float scale = 0.044194173824159216f;  // 1/sqrt(512)
            float s = 0.f;
#pragma unroll
            for (int w8 = 0; w8 < 8; w8++) s += red[w8][p];
            s *= scale;
            float mx = s;
#pragma unroll
            for (int off = 8; off >= 1; off >>= 1)
                mx = fmaxf(mx, __shfl_xor_sync(0xffffffffu, mx, off));
            float e = expf(s - mx);
            float tot = e;
#pragma unroll
            for (int off = 8; off >= 1; off >>= 1)
                tot += __shfl_xor_sync(0xffffffffu, tot, off);
            if (lane < 16) aw[p] = e / tot;
        }
        __syncthreads();

        float wl[16];
#pragma unroll
        for (int p = 0; p < 16; p++) wl[p] = aw[p];

        float* ao = g_attn + (size_t)n * Hh;
#pragma unroll
        for (int i = 0; i < 2; i++) {
            float s = 0.f;
#pragma unroll
            for (int q = 0; q < 4; q++) {
                float4 v = cur[i * 4 + q];
                s += v.x * wl[q * 4 + 0] + v.y * wl[q * 4 + 1]
                   + v.z * wl[q * 4 + 2] + v.w * wl[q * 4 + 3];
            }
            ao[tid + i * 256] = s;
        }

        if (rr < 3) {
#pragma unroll
            for (int q = 0; q < 8; q++) cur[q] = nxt[q];
            hcur[0] = hnxt[0]; hcur[1] = hnxt[1];
        }
    }
}

// ---------------------------------------------------------------------------
// fused step GEMM + gates (round-4 proven config: 256 threads, 2x4 warp grid,
// 32x32 warp tiles), pipeline deepened to 4 stages / wait_group 2.
// ---------------------------------------------------------------------------
#define ASTR 20
#define BSTR 136
#define A_FLOATS (64 * ASTR)
#define STAGE_FLOATS (64 * ASTR + 16 * BSTR)  // 3456 floats
#define NSTAGES 4
#define ITERS 96

#define CP_ASYNC16(dst, src) \
    asm volatile("cp.async.cg.shared.global [%0], [%1], 16;\n" :: "r"(dst), "l"(src))
#define CP_COMMIT() asm volatile("cp.async.commit_group;\n")
#define CP_WAIT2()  asm volatile("cp.async.wait_group 2;\n")

__device__ __forceinline__ uint32_t smem_u32(const void* p) {
    return (uint32_t)__cvta_generic_to_shared(p);
}

__global__ __launch_bounds__(256, 1) void step_kernel(
    const float* __restrict__ x, const float* __restrict__ Wx,
    const float* __restrict__ Wh, const float* __restrict__ Wattn,
    const float* __restrict__ bias, float* __restrict__ out, int t, int pi)
{
    __shared__ __align__(16) float sm[NSTAGES * STAGE_FLOATS];
    const int tid = threadIdx.x;
    const int j0 = blockIdx.x * 32;
    const int n0 = blockIdx.y * 64;
    const float* h_in = g_h[pi];
    const float* c_in = g_c[pi];
    float* h_out = g_h[pi ^ 1];
    float* c_out = g_c[pi ^ 1];

    const float* xbase = x + (size_t)n0 * Tt * Dd + (size_t)t * Dd;
    const int am = tid >> 2, akq = (tid & 3) * 4;

    const int lane = tid & 31, wid = tid >> 5;
    const int wm = wid & 1, wn = wid >> 1;
    const int gid = lane >> 2, tg = lane & 3;

    float acc[2][4][4];
#pragma unroll
    for (int fm = 0; fm < 2; fm++)
#pragma unroll
        for (int fn = 0; fn < 4; fn++)
#pragma unroll
            for (int e = 0; e < 4; e++) acc[fm][fn][e] = 0.f;

    auto issue = [&](int i) {
        float* stg = sm + (i % NSTAGES) * STAGE_FLOATS;
        int seg = i >> 5;
        int kl = (i & 31) << 4;
        const float* Ab; size_t astr; const float* W;
        if (seg == 0)      { Ab = xbase;                        astr = (size_t)Tt * Dd; W = Wx; }
        else if (seg == 1) { Ab = h_in   + (size_t)n0 * Hh;     astr = Hh;              W = Wh; }
        else               { Ab = g_attn + (size_t)n0 * Hh;     astr = Hh;              W = Wattn; }
        const float* asrc = Ab + (size_t)am * astr + kl + akq;
        CP_ASYNC16(smem_u32(stg + am * ASTR + akq), asrc);
        float* Bst = stg + A_FLOATS;
#pragma unroll
        for (int j = 0; j < 2; j++) {
            int e = tid + j * 256;
            int k = e >> 5, n4 = e & 31;
            const float* bsrc = W + (size_t)(kl + k) * FH + (n4 >> 3) * 512 + j0 + (n4 & 7) * 4;
            CP_ASYNC16(smem_u32(Bst + k * BSTR + n4 * 4), bsrc);
        }
    };

    issue(0); CP_COMMIT();
    issue(1); CP_COMMIT();
    issue(2); CP_COMMIT();

    for (int i = 0; i < ITERS; i++) {
        CP_WAIT2();
        __syncthreads();
        const float* As = sm + (i % NSTAGES) * STAGE_FLOATS;
        const float* Bs = As + A_FLOATS;
#pragma unroll
        for (int k8 = 0; k8 < 2; k8++) {
            int kb = k8 * 8;
            uint32_t a[2][4], bf[4][2];
#pragma unroll
            for (int fm = 0; fm < 2; fm++) {
                int row = wm * 32 + fm * 16 + gid;
                a[fm][0] = __float_as_uint(As[row * ASTR + kb + tg]);
                a[fm][1] = __float_as_uint(As[(row + 8) * ASTR + kb + tg]);
                a[fm][2] = __float_as_uint(As[row * ASTR + kb + tg + 4]);
                a[fm][3] = __float_as_uint(As[(row + 8) * ASTR + kb + tg + 4]);
            }
#pragma unroll
            for (int fn = 0; fn < 4; fn++) {
                int col = wn * 32 + fn * 8 + gid;
                bf[fn][0] = __float_as_uint(Bs[(kb + tg) * BSTR + col]);
                bf[fn][1] = __float_as_uint(Bs[(kb + tg + 4) * BSTR + col]);
            }
#pragma unroll
            for (int fm = 0; fm < 2; fm++)
#pragma unroll
                for (int fn = 0; fn < 4; fn++) {
                    asm volatile(
                        "mma.sync.aligned.m16n8k8.row.col.f32.tf32.tf32.f32 "
                        "{%0,%1,%2,%3}, {%4,%5,%6,%7}, {%8,%9}, {%0,%1,%2,%3};\n"
                        : "+f"(acc[fm][fn][0]), "+f"(acc[fm][fn][1]),
                          "+f"(acc[fm][fn][2]), "+f"(acc[fm][fn][3])
                        : "r"(a[fm][0]), "r"(a[fm][1]), "r"(a[fm][2]), "r"(a[fm][3]),
                          "r"(bf[fn][0]), "r"(bf[fn][1]));
                }
        }
        if (i + 3 < ITERS) issue(i + 3);
        CP_COMMIT();
    }

    __syncthreads();
    // stash a-tile (64 x 128) in smem for gate gathering
    float (*atile)[132] = (float(*)[132])sm;
#pragma unroll
    for (int fm = 0; fm < 2; fm++)
#pragma unroll
        for (int fn = 0; fn < 4; fn++) {
            int R = wm * 32 + fm * 16 + gid, C = wn * 32 + fn * 8 + tg * 2;
            atile[R][C]         = acc[fm][fn][0];
            atile[R][C + 1]     = acc[fm][fn][1];
            atile[R + 8][C]     = acc[fm][fn][2];
            atile[R + 8][C + 1] = acc[fm][fn][3];
        }
    __syncthreads();

    {
        int col = tid & 31;
        int r0 = tid >> 5;
        float bi = bias[j0 + col];
        float bff = bias[512 + j0 + col];
        float bo = bias[1024 + j0 + col];
        float bg = bias[1536 + j0 + col];
#pragma unroll
        for (int q = 0; q < 8; q++) {
            int row = r0 + q * 8;
            float vi = atile[row][col]      + bi;
            float vf = atile[row][col + 32] + bff;
            float vo = atile[row][col + 64] + bo;
            float vg = atile[row][col + 96] + bg;
            float ig = 1.f / (1.f + expf(-vi));
            float fg = 1.f / (1.f + expf(-vf));
            float og = 1.f / (1.f + expf(-vo));
            float gg = tanhf(vg);
            int n = n0 + row, hc = j0 + col;
            float cold = c_in[n * Hh + hc];
            float cn = fg * cold + ig * gg;
            float hn = og * tanhf(cn);
            c_out[n * Hh + hc] = cn;
            h_out[n * Hh + hc] = hn;
            out[((size_t)n * Tt + t) * Hh + hc] = hn;
        }
    }
}

// ---------------------------------------------------------------------------
extern "C" void kernel_launch(void* const* d_in, const int* in_sizes, int n_in,
                              void* d_out, int out_size) {
    const float* x     = (const float*)d_in[0];
    const float* A     = (const float*)d_in[1];
    const float* Wx    = (const float*)d_in[2];
    const float* Wh    = (const float*)d_in[3];
    const float* Wattn = (const float*)d_in[4];
    const float* b     = (const float*)d_in[5];
    float* out = (float*)d_out;

    init_kernel<<<Nb, 128>>>(A);
    for (int t = 0; t < Tt; t++) {
        int pi = t & 1;
        attn_kernel<<<128, 256>>>(A, pi);
        step_kernel<<<dim3(16, 8), 256>>>(x, Wx, Wh, Wattn, b, out, t, pi);
    }
}

// round 9
// speedup vs baseline: 1.0044x; 1.0044x over previous
#include <cuda_runtime.h>
#include <cstdint>
#include <math.h>

#define Nb 512
#define Tt 64
#define Dd 512
#define Hh 512
#define FH 2048

// Persistent state (device globals: no allocations allowed)
__device__ float g_h[2][Nb * Hh];
__device__ float g_c[2][Nb * Hh];
__device__ float g_attn[Nb * Hh];

// ---------------------------------------------------------------------------
// init: h0 = c0 = mean over the 16 spatial positions of A
// ---------------------------------------------------------------------------
__global__ __launch_bounds__(128) void init_kernel(const float* __restrict__ A) {
    int n = blockIdx.x, tid = threadIdx.x;
    const float4* base = (const float4*)(A + (size_t)n * Hh * 16);
#pragma unroll
    for (int i = 0; i < 4; i++) {
        int r = tid + i * 128;
        float4 v0 = base[r * 4 + 0], v1 = base[r * 4 + 1];
        float4 v2 = base[r * 4 + 2], v3 = base[r * 4 + 3];
        float s = (v0.x + v0.y + v0.z + v0.w) + (v1.x + v1.y + v1.z + v1.w)
                + (v2.x + v2.y + v2.z + v2.w) + (v3.x + v3.y + v3.z + v3.w);
        float m = s * (1.0f / 16.0f);
        g_h[0][n * Hh + r] = m;
        g_c[0][n * Hh + r] = m;
    }
}

// ---------------------------------------------------------------------------
// attention (proven round-4 version): one block per batch row, 128 threads,
// A row in registers, read once.
// ---------------------------------------------------------------------------
__global__ __launch_bounds__(128) void attn_kernel(const float* __restrict__ A, int pi) {
    int n = blockIdx.x, tid = threadIdx.x;
    int lane = tid & 31, warp = tid >> 5;
    const float* hbuf = g_h[pi] + (size_t)n * Hh;
    const float4* base = (const float4*)(A + (size_t)n * Hh * 16);

    float Av[4][16];
    float hv[4];
    float part[16];
#pragma unroll
    for (int p = 0; p < 16; p++) part[p] = 0.f;

#pragma unroll
    for (int i = 0; i < 4; i++) {
        int r = tid + i * 128;
#pragma unroll
        for (int q = 0; q < 4; q++) {
            float4 v = base[r * 4 + q];
            Av[i][q * 4 + 0] = v.x; Av[i][q * 4 + 1] = v.y;
            Av[i][q * 4 + 2] = v.z; Av[i][q * 4 + 3] = v.w;
        }
        hv[i] = hbuf[r];
#pragma unroll
        for (int p = 0; p < 16; p++) part[p] += hv[i] * Av[i][p];
    }

#pragma unroll
    for (int off = 16; off >= 1; off >>= 1)
#pragma unroll
        for (int p = 0; p < 16; p++)
            part[p] += __shfl_xor_sync(0xffffffffu, part[p], off);

    __shared__ float red[4][16];
    __shared__ float w[16];
    if (lane == 0) {
#pragma unroll
        for (int p = 0; p < 16; p++) red[warp][p] = part[p];
    }
    __syncthreads();
    if (tid == 0) {
        const float scale = 0.044194173824159216f;  // 1/sqrt(512)
        float sc[16];
        float mx = -1e30f;
#pragma unroll
        for (int p = 0; p < 16; p++) {
            sc[p] = (red[0][p] + red[1][p] + red[2][p] + red[3][p]) * scale;
            mx = fmaxf(mx, sc[p]);
        }
        float s = 0.f;
#pragma unroll
        for (int p = 0; p < 16; p++) { float e = expf(sc[p] - mx); w[p] = e; s += e; }
        float inv = 1.f / s;
#pragma unroll
        for (int p = 0; p < 16; p++) w[p] *= inv;
    }
    __syncthreads();

    float wl[16];
#pragma unroll
    for (int p = 0; p < 16; p++) wl[p] = w[p];
    float* ao = g_attn + (size_t)n * Hh;
#pragma unroll
    for (int i = 0; i < 4; i++) {
        float s = 0.f;
#pragma unroll
        for (int p = 0; p < 16; p++) s += Av[i][p] * wl[p];
        ao[tid + i * 128] = s;
    }
}

// ---------------------------------------------------------------------------
// fused step GEMM + gates, RE-TILED: CTA tile 128 rows x 32 h-cols (128 a-cols),
// 512 threads / 16 warps in a 4x4 grid of 32x32 warp tiles (same per-warp
// inner loop as the proven round-4 kernel, ratio LDS:MMA = 2). Grid (16,4)=64
// CTAs -> 4 warps/SMSP for latency hiding, half the W L2 traffic.
// ---------------------------------------------------------------------------
#define ASTR 20
#define BSTR 136
#define A_FLOATS (128 * ASTR)                  // 2560
#define STAGE_FLOATS (128 * ASTR + 16 * BSTR)  // 4736 floats
#define NSTAGES 3
#define ITERS 96
// smem: max(pipeline = 3*4736 = 14208, epilogue atile = 128*132 = 16896)
#define SMEM_FLOATS 16896

#define CP_ASYNC16(dst, src) \
    asm volatile("cp.async.cg.shared.global [%0], [%1], 16;\n" :: "r"(dst), "l"(src))
#define CP_COMMIT() asm volatile("cp.async.commit_group;\n")
#define CP_WAIT1()  asm volatile("cp.async.wait_group 1;\n")

__device__ __forceinline__ uint32_t smem_u32(const void* p) {
    return (uint32_t)__cvta_generic_to_shared(p);
}

__global__ __launch_bounds__(512, 1) void step_kernel(
    const float* __restrict__ x, const float* __restrict__ Wx,
    const float* __restrict__ Wh, const float* __restrict__ Wattn,
    const float* __restrict__ bias, float* __restrict__ out, int t, int pi)
{
    __shared__ __align__(16) float sm[SMEM_FLOATS];
    const int tid = threadIdx.x;
    const int j0 = blockIdx.x * 32;
    const int n0 = blockIdx.y * 128;
    const float* h_in = g_h[pi];
    const float* c_in = g_c[pi];
    float* h_out = g_h[pi ^ 1];
    float* c_out = g_c[pi ^ 1];

    const float* xbase = x + (size_t)n0 * Tt * Dd + (size_t)t * Dd;
    // A-tile loader: 128 rows x 16 k-floats, one 16B chunk per thread
    const int am = tid >> 2, akq = (tid & 3) * 4;
    // B-tile loader: 16 k-rows x 32 chunks, one 16B chunk per thread
    const int bk = tid >> 5, bn4 = tid & 31;

    const int lane = tid & 31, wid = tid >> 5;
    const int wm = wid & 3, wn = wid >> 2;     // 4x4 warp grid, 32x32 tiles
    const int gid = lane >> 2, tg = lane & 3;

    float acc[2][4][4];
#pragma unroll
    for (int fm = 0; fm < 2; fm++)
#pragma unroll
        for (int fn = 0; fn < 4; fn++)
#pragma unroll
            for (int e = 0; e < 4; e++) acc[fm][fn][e] = 0.f;

    auto issue = [&](int i) {
        float* stg = sm + (i % NSTAGES) * STAGE_FLOATS;
        int seg = i >> 5;
        int kl = (i & 31) << 4;
        const float* Ab; size_t astr; const float* W;
        if (seg == 0)      { Ab = xbase;                        astr = (size_t)Tt * Dd; W = Wx; }
        else if (seg == 1) { Ab = h_in   + (size_t)n0 * Hh;     astr = Hh;              W = Wh; }
        else               { Ab = g_attn + (size_t)n0 * Hh;     astr = Hh;              W = Wattn; }
        const float* asrc = Ab + (size_t)am * astr + kl + akq;
        CP_ASYNC16(smem_u32(stg + am * ASTR + akq), asrc);
        float* Bst = stg + A_FLOATS;
        const float* bsrc = W + (size_t)(kl + bk) * FH + (bn4 >> 3) * 512 + j0 + (bn4 & 7) * 4;
        CP_ASYNC16(smem_u32(Bst + bk * BSTR + bn4 * 4), bsrc);
    };

    issue(0); CP_COMMIT();
    issue(1); CP_COMMIT();

    for (int i = 0; i < ITERS; i++) {
        CP_WAIT1();
        __syncthreads();
        const float* As = sm + (i % NSTAGES) * STAGE_FLOATS;
        const float* Bs = As + A_FLOATS;
#pragma unroll
        for (int k8 = 0; k8 < 2; k8++) {
            int kb = k8 * 8;
            uint32_t a[2][4], bf[4][2];
#pragma unroll
            for (int fm = 0; fm < 2; fm++) {
                int row = wm * 32 + fm * 16 + gid;
                a[fm][0] = __float_as_uint(As[row * ASTR + kb + tg]);
                a[fm][1] = __float_as_uint(As[(row + 8) * ASTR + kb + tg]);
                a[fm][2] = __float_as_uint(As[row * ASTR + kb + tg + 4]);
                a[fm][3] = __float_as_uint(As[(row + 8) * ASTR + kb + tg + 4]);
            }
#pragma unroll
            for (int fn = 0; fn < 4; fn++) {
                int col = wn * 32 + fn * 8 + gid;
                bf[fn][0] = __float_as_uint(Bs[(kb + tg) * BSTR + col]);
                bf[fn][1] = __float_as_uint(Bs[(kb + tg + 4) * BSTR + col]);
            }
#pragma unroll
            for (int fm = 0; fm < 2; fm++)
#pragma unroll
                for (int fn = 0; fn < 4; fn++) {
                    asm volatile(
                        "mma.sync.aligned.m16n8k8.row.col.f32.tf32.tf32.f32 "
                        "{%0,%1,%2,%3}, {%4,%5,%6,%7}, {%8,%9}, {%0,%1,%2,%3};\n"
                        : "+f"(acc[fm][fn][0]), "+f"(acc[fm][fn][1]),
                          "+f"(acc[fm][fn][2]), "+f"(acc[fm][fn][3])
                        : "r"(a[fm][0]), "r"(a[fm][1]), "r"(a[fm][2]), "r"(a[fm][3]),
                          "r"(bf[fn][0]), "r"(bf[fn][1]));
                }
        }
        if (i + 2 < ITERS) issue(i + 2);
        CP_COMMIT();
    }

    __syncthreads();
    // stash a-tile (128 x 128) in smem for gate gathering
    float (*atile)[132] = (float(*)[132])sm;
#pragma unroll
    for (int fm = 0; fm < 2; fm++)
#pragma unroll
        for (int fn = 0; fn < 4; fn++) {
            int R = wm * 32 + fm * 16 + gid, C = wn * 32 + fn * 8 + tg * 2;
            atile[R][C]         = acc[fm][fn][0];
            atile[R][C + 1]     = acc[fm][fn][1];
            atile[R + 8][C]     = acc[fm][fn][2];
            atile[R + 8][C + 1] = acc[fm][fn][3];
        }
    __syncthreads();

    {
        int col = tid & 31;
        int r0 = tid >> 5;          // 0..15
        float bi = bias[j0 + col];
        float bff = bias[512 + j0 + col];
        float bo = bias[1024 + j0 + col];
        float bg = bias[1536 + j0 + col];
#pragma unroll
        for (int q = 0; q < 8; q++) {
            int row = r0 + q * 16;
            float vi = atile[row][col]      + bi;
            float vf = atile[row][col + 32] + bff;
            float vo = atile[row][col + 64] + bo;
            float vg = atile[row][col + 96] + bg;
            float ig = 1.f / (1.f + expf(-vi));
            float fg = 1.f / (1.f + expf(-vf));
            float og = 1.f / (1.f + expf(-vo));
            float gg = tanhf(vg);
            int n = n0 + row, hc = j0 + col;
            float cold = c_in[n * Hh + hc];
            float cn = fg * cold + ig * gg;
            float hn = og * tanhf(cn);
            c_out[n * Hh + hc] = cn;
            h_out[n * Hh + hc] = hn;
            out[((size_t)n * Tt + t) * Hh + hc] = hn;
        }
    }
}

// ---------------------------------------------------------------------------
extern "C" void kernel_launch(void* const* d_in, const int* in_sizes, int n_in,
                              void* d_out, int out_size) {
    const float* x     = (const float*)d_in[0];
    const float* A     = (const float*)d_in[1];
    const float* Wx    = (const float*)d_in[2];
    const float* Wh    = (const float*)d_in[3];
    const float* Wattn = (const float*)d_in[4];
    const float* b     = (const float*)d_in[5];
    float* out = (float*)d_out;

    init_kernel<<<Nb, 128>>>(A);
    for (int t = 0; t < Tt; t++) {
        int pi = t & 1;
        attn_kernel<<<Nb, 128>>>(A, pi);
        step_kernel<<<dim3(16, 4), 512>>>(x, Wx, Wh, Wattn, b, out, t, pi);
    }
}

// round 10
// speedup vs baseline: 1.4282x; 1.4219x over previous
#include <cuda_runtime.h>
#include <cstdint>
#include <math.h>

#define Nb 512
#define Tt 64
#define Dd 512
#define Hh 512
#define FH 2048

// Persistent state (device globals: no allocations allowed)
__device__ float g_h[2][Nb * Hh];
__device__ float g_c[2][Nb * Hh];
__device__ float g_attn[Nb * Hh];
__device__ float g_xw[Nb * FH];   // x(t) @ Wx, gathered-gate column layout (natural FH cols)

#define ASTR 20
#define BSTR 136
#define A_FLOATS (64 * ASTR)
#define STAGE_FLOATS (64 * ASTR + 16 * BSTR)  // 3456 floats
#define NSTAGES 3

#define CP_ASYNC16(dst, src) \
    asm volatile("cp.async.cg.shared.global [%0], [%1], 16;\n" :: "r"(dst), "l"(src))
#define CP_COMMIT() asm volatile("cp.async.commit_group;\n")
#define CP_WAIT1()  asm volatile("cp.async.wait_group 1;\n")

__device__ __forceinline__ uint32_t smem_u32(const void* p) {
    return (uint32_t)__cvta_generic_to_shared(p);
}

// ---------------------------------------------------------------------------
// init: h0 = c0 = mean over the 16 spatial positions of A
// ---------------------------------------------------------------------------
__global__ __launch_bounds__(128) void init_kernel(const float* __restrict__ A) {
    int n = blockIdx.x, tid = threadIdx.x;
    const float4* base = (const float4*)(A + (size_t)n * Hh * 16);
#pragma unroll
    for (int i = 0; i < 4; i++) {
        int r = tid + i * 128;
        float4 v0 = base[r * 4 + 0], v1 = base[r * 4 + 1];
        float4 v2 = base[r * 4 + 2], v3 = base[r * 4 + 3];
        float s = (v0.x + v0.y + v0.z + v0.w) + (v1.x + v1.y + v1.z + v1.w)
                + (v2.x + v2.y + v2.z + v2.w) + (v3.x + v3.y + v3.z + v3.w);
        float m = s * (1.0f / 16.0f);
        g_h[0][n * Hh + r] = m;
        g_c[0][n * Hh + r] = m;
    }
}

// ---------------------------------------------------------------------------
// fused attn + xW kernel. 640 blocks x 256 threads.
//   blocks [0,512): attention for batch row n = blockIdx (round-7 proven body)
//   blocks [512,640): xW GEMM CTA (round-4 proven mainloop, x/Wx only, 32 iters)
// Both depend only on t-1 state / static inputs -> freely concurrent.
// ---------------------------------------------------------------------------
__global__ __launch_bounds__(256, 2) void attn_xw_kernel(
    const float* __restrict__ A, const float* __restrict__ x,
    const float* __restrict__ Wx, int t, int pi)
{
    __shared__ __align__(16) float sm[NSTAGES * STAGE_FLOATS];
    const int tid = threadIdx.x;

    if (blockIdx.x < 512) {
        // ===================== attention path ===========================
        const int n = blockIdx.x;
        const int lane = tid & 31, warp = tid >> 5;
        const float* hbuf = g_h[pi] + (size_t)n * Hh;
        const float4* base = (const float4*)(A + (size_t)n * Hh * 16);

        float (*red)[16] = (float(*)[16])sm;    // 8x16
        float* aw = sm + 128;                   // 16

        float4 av[2][4];
        float hv[2];
#pragma unroll
        for (int i = 0; i < 2; i++) {
            int r = tid + i * 256;
#pragma unroll
            for (int q = 0; q < 4; q++) av[i][q] = base[r * 4 + q];
            hv[i] = hbuf[r];
        }

        float Av[2][16];
#pragma unroll
        for (int i = 0; i < 2; i++)
#pragma unroll
            for (int q = 0; q < 4; q++) {
                Av[i][q * 4 + 0] = av[i][q].x; Av[i][q * 4 + 1] = av[i][q].y;
                Av[i][q * 4 + 2] = av[i][q].z; Av[i][q * 4 + 3] = av[i][q].w;
            }

        float part[16];
#pragma unroll
        for (int p = 0; p < 16; p++) part[p] = hv[0] * Av[0][p] + hv[1] * Av[1][p];

#pragma unroll
        for (int off = 16; off >= 1; off >>= 1)
#pragma unroll
            for (int p = 0; p < 16; p++)
                part[p] += __shfl_xor_sync(0xffffffffu, part[p], off);

        if (lane == 0) {
#pragma unroll
            for (int p = 0; p < 16; p++) red[warp][p] = part[p];
        }
        __syncthreads();

        if (warp == 0) {
            int p = lane & 15;
            const float scale = 0.044194173824159216f;  // 1/sqrt(512)
            float s = 0.f;
#pragma unroll
            for (int w8 = 0; w8 < 8; w8++) s += red[w8][p];
            s *= scale;
            float mx = s;
#pragma unroll
            for (int off = 8; off >= 1; off >>= 1)
                mx = fmaxf(mx, __shfl_xor_sync(0xffffffffu, mx, off));
            float e = expf(s - mx);
            float tot = e;
#pragma unroll
            for (int off = 8; off >= 1; off >>= 1)
                tot += __shfl_xor_sync(0xffffffffu, tot, off);
            if (lane < 16) aw[p] = e / tot;
        }
        __syncthreads();

        float wl[16];
#pragma unroll
        for (int p = 0; p < 16; p++) wl[p] = aw[p];
        float* ao = g_attn + (size_t)n * Hh;
#pragma unroll
        for (int i = 0; i < 2; i++) {
            float s = 0.f;
#pragma unroll
            for (int p = 0; p < 16; p++) s += Av[i][p] * wl[p];
            ao[tid + i * 256] = s;
        }
    } else {
        // ===================== xW GEMM path =============================
        const int b = blockIdx.x - 512;
        const int j0 = (b & 15) * 32;
        const int n0 = (b >> 4) * 64;
        const float* xbase = x + (size_t)n0 * Tt * Dd + (size_t)t * Dd;
        const int am = tid >> 2, akq = (tid & 3) * 4;

        const int lane = tid & 31, wid = tid >> 5;
        const int wm = wid & 1, wn = wid >> 1;
        const int gid = lane >> 2, tg = lane & 3;

        float acc[2][4][4];
#pragma unroll
        for (int fm = 0; fm < 2; fm++)
#pragma unroll
            for (int fn = 0; fn < 4; fn++)
#pragma unroll
                for (int e = 0; e < 4; e++) acc[fm][fn][e] = 0.f;

        auto issue = [&](int i) {
            float* stg = sm + (i % NSTAGES) * STAGE_FLOATS;
            int kl = i << 4;
            const float* asrc = xbase + (size_t)am * (Tt * Dd) + kl + akq;
            CP_ASYNC16(smem_u32(stg + am * ASTR + akq), asrc);
            float* Bst = stg + A_FLOATS;
#pragma unroll
            for (int j = 0; j < 2; j++) {
                int e = tid + j * 256;
                int k = e >> 5, n4 = e & 31;
                const float* bsrc = Wx + (size_t)(kl + k) * FH + (n4 >> 3) * 512 + j0 + (n4 & 7) * 4;
                CP_ASYNC16(smem_u32(Bst + k * BSTR + n4 * 4), bsrc);
            }
        };

        issue(0); CP_COMMIT();
        issue(1); CP_COMMIT();

        for (int i = 0; i < 32; i++) {
            CP_WAIT1();
            __syncthreads();
            const float* As = sm + (i % NSTAGES) * STAGE_FLOATS;
            const float* Bs = As + A_FLOATS;
#pragma unroll
            for (int k8 = 0; k8 < 2; k8++) {
                int kb = k8 * 8;
                uint32_t a[2][4], bf[4][2];
#pragma unroll
                for (int fm = 0; fm < 2; fm++) {
                    int row = wm * 32 + fm * 16 + gid;
                    a[fm][0] = __float_as_uint(As[row * ASTR + kb + tg]);
                    a[fm][1] = __float_as_uint(As[(row + 8) * ASTR + kb + tg]);
                    a[fm][2] = __float_as_uint(As[row * ASTR + kb + tg + 4]);
                    a[fm][3] = __float_as_uint(As[(row + 8) * ASTR + kb + tg + 4]);
                }
#pragma unroll
                for (int fn = 0; fn < 4; fn++) {
                    int col = wn * 32 + fn * 8 + gid;
                    bf[fn][0] = __float_as_uint(Bs[(kb + tg) * BSTR + col]);
                    bf[fn][1] = __float_as_uint(Bs[(kb + tg + 4) * BSTR + col]);
                }
#pragma unroll
                for (int fm = 0; fm < 2; fm++)
#pragma unroll
                    for (int fn = 0; fn < 4; fn++) {
                        asm volatile(
                            "mma.sync.aligned.m16n8k8.row.col.f32.tf32.tf32.f32 "
                            "{%0,%1,%2,%3}, {%4,%5,%6,%7}, {%8,%9}, {%0,%1,%2,%3};\n"
                            : "+f"(acc[fm][fn][0]), "+f"(acc[fm][fn][1]),
                              "+f"(acc[fm][fn][2]), "+f"(acc[fm][fn][3])
                            : "r"(a[fm][0]), "r"(a[fm][1]), "r"(a[fm][2]), "r"(a[fm][3]),
                              "r"(bf[fn][0]), "r"(bf[fn][1]));
                    }
            }
            if (i + 2 < 32) issue(i + 2);
            CP_COMMIT();
        }

        // write raw tile to g_xw: col C -> fh col = wn*512 + j0 + fn*8 + tg*2
#pragma unroll
        for (int fm = 0; fm < 2; fm++)
#pragma unroll
            for (int fn = 0; fn < 4; fn++) {
                int R = wm * 32 + fm * 16 + gid;
                int fc = wn * 512 + j0 + fn * 8 + tg * 2;
                *(float2*)&g_xw[(size_t)(n0 + R) * FH + fc] =
                    make_float2(acc[fm][fn][0], acc[fm][fn][1]);
                *(float2*)&g_xw[(size_t)(n0 + R + 8) * FH + fc] =
                    make_float2(acc[fm][fn][2], acc[fm][fn][3]);
            }
    }
}

// ---------------------------------------------------------------------------
// sequential step: K=1024 (h-seg + attn-seg), acc initialized from g_xw,
// round-4 proven mainloop + gate epilogue. Grid (16,8), 256 threads.
// ---------------------------------------------------------------------------
__global__ __launch_bounds__(256, 1) void step_kernel(
    const float* __restrict__ Wh, const float* __restrict__ Wattn,
    const float* __restrict__ bias, float* __restrict__ out, int t, int pi)
{
    __shared__ __align__(16) float sm[NSTAGES * STAGE_FLOATS];
    const int tid = threadIdx.x;
    const int j0 = blockIdx.x * 32;
    const int n0 = blockIdx.y * 64;
    const float* h_in = g_h[pi];
    const float* c_in = g_c[pi];
    float* h_out = g_h[pi ^ 1];
    float* c_out = g_c[pi ^ 1];

    const int am = tid >> 2, akq = (tid & 3) * 4;
    const int lane = tid & 31, wid = tid >> 5;
    const int wm = wid & 1, wn = wid >> 1;
    const int gid = lane >> 2, tg = lane & 3;

    // acc init from g_xw (each thread loads its owned elements)
    float acc[2][4][4];
#pragma unroll
    for (int fm = 0; fm < 2; fm++)
#pragma unroll
        for (int fn = 0; fn < 4; fn++) {
            int R = wm * 32 + fm * 16 + gid;
            int fc = wn * 512 + j0 + fn * 8 + tg * 2;
            float2 v0 = *(const float2*)&g_xw[(size_t)(n0 + R) * FH + fc];
            float2 v1 = *(const float2*)&g_xw[(size_t)(n0 + R + 8) * FH + fc];
            acc[fm][fn][0] = v0.x; acc[fm][fn][1] = v0.y;
            acc[fm][fn][2] = v1.x; acc[fm][fn][3] = v1.y;
        }

    auto issue = [&](int i) {
        float* stg = sm + (i % NSTAGES) * STAGE_FLOATS;
        int seg = i >> 5;
        int kl = (i & 31) << 4;
        const float* Ab; const float* W;
        if (seg == 0) { Ab = h_in   + (size_t)n0 * Hh; W = Wh; }
        else          { Ab = g_attn + (size_t)n0 * Hh; W = Wattn; }
        const float* asrc = Ab + (size_t)am * Hh + kl + akq;
        CP_ASYNC16(smem_u32(stg + am * ASTR + akq), asrc);
        float* Bst = stg + A_FLOATS;
#pragma unroll
        for (int j = 0; j < 2; j++) {
            int e = tid + j * 256;
            int k = e >> 5, n4 = e & 31;
            const float* bsrc = W + (size_t)(kl + k) * FH + (n4 >> 3) * 512 + j0 + (n4 & 7) * 4;
            CP_ASYNC16(smem_u32(Bst + k * BSTR + n4 * 4), bsrc);
        }
    };

    issue(0); CP_COMMIT();
    issue(1); CP_COMMIT();

    for (int i = 0; i < 64; i++) {
        CP_WAIT1();
        __syncthreads();
        const float* As = sm + (i % NSTAGES) * STAGE_FLOATS;
        const float* Bs = As + A_FLOATS;
#pragma unroll
        for (int k8 = 0; k8 < 2; k8++) {
            int kb = k8 * 8;
            uint32_t a[2][4], bf[4][2];
#pragma unroll
            for (int fm = 0; fm < 2; fm++) {
                int row = wm * 32 + fm * 16 + gid;
                a[fm][0] = __float_as_uint(As[row * ASTR + kb + tg]);
                a[fm][1] = __float_as_uint(As[(row + 8) * ASTR + kb + tg]);
                a[fm][2] = __float_as_uint(As[row * ASTR + kb + tg + 4]);
                a[fm][3] = __float_as_uint(As[(row + 8) * ASTR + kb + tg + 4]);
            }
#pragma unroll
            for (int fn = 0; fn < 4; fn++) {
                int col = wn * 32 + fn * 8 + gid;
                bf[fn][0] = __float_as_uint(Bs[(kb + tg) * BSTR + col]);
                bf[fn][1] = __float_as_uint(Bs[(kb + tg + 4) * BSTR + col]);
            }
#pragma unroll
            for (int fm = 0; fm < 2; fm++)
#pragma unroll
                for (int fn = 0; fn < 4; fn++) {
                    asm volatile(
                        "mma.sync.aligned.m16n8k8.row.col.f32.tf32.tf32.f32 "
                        "{%0,%1,%2,%3}, {%4,%5,%6,%7}, {%8,%9}, {%0,%1,%2,%3};\n"
                        : "+f"(acc[fm][fn][0]), "+f"(acc[fm][fn][1]),
                          "+f"(acc[fm][fn][2]), "+f"(acc[fm][fn][3])
                        : "r"(a[fm][0]), "r"(a[fm][1]), "r"(a[fm][2]), "r"(a[fm][3]),
                          "r"(bf[fn][0]), "r"(bf[fn][1]));
                }
        }
        if (i + 2 < 64) issue(i + 2);
        CP_COMMIT();
    }

    __syncthreads();
    // stash a-tile (64 x 128) in smem for gate gathering
    float (*atile)[132] = (float(*)[132])sm;
#pragma unroll
    for (int fm = 0; fm < 2; fm++)
#pragma unroll
        for (int fn = 0; fn < 4; fn++) {
            int R = wm * 32 + fm * 16 + gid, C = wn * 32 + fn * 8 + tg * 2;
            atile[R][C]         = acc[fm][fn][0];
            atile[R][C + 1]     = acc[fm][fn][1];
            atile[R + 8][C]     = acc[fm][fn][2];
            atile[R + 8][C + 1] = acc[fm][fn][3];
        }
    __syncthreads();

    {
        int col = tid & 31;
        int r0 = tid >> 5;
        float bi = bias[j0 + col];
        float bff = bias[512 + j0 + col];
        float bo = bias[1024 + j0 + col];
        float bg = bias[1536 + j0 + col];
#pragma unroll
        for (int q = 0; q < 8; q++) {
            int row = r0 + q * 8;
            float vi = atile[row][col]      + bi;
            float vf = atile[row][col + 32] + bff;
            float vo = atile[row][col + 64] + bo;
            float vg = atile[row][col + 96] + bg;
            float ig = 1.f / (1.f + expf(-vi));
            float fg = 1.f / (1.f + expf(-vf));
            float og = 1.f / (1.f + expf(-vo));
            float gg = tanhf(vg);
            int n = n0 + row, hc = j0 + col;
            float cold = c_in[n * Hh + hc];
            float cn = fg * cold + ig * gg;
            float hn = og * tanhf(cn);
            c_out[n * Hh + hc] = cn;
            h_out[n * Hh + hc] = hn;
            out[((size_t)n * Tt + t) * Hh + hc] = hn;
        }
    }
}

// ---------------------------------------------------------------------------
extern "C" void kernel_launch(void* const* d_in, const int* in_sizes, int n_in,
                              void* d_out, int out_size) {
    const float* x     = (const float*)d_in[0];
    const float* A     = (const float*)d_in[1];
    const float* Wx    = (const float*)d_in[2];
    const float* Wh    = (const float*)d_in[3];
    const float* Wattn = (const float*)d_in[4];
    const float* b     = (const float*)d_in[5];
    float* out = (float*)d_out;

    init_kernel<<<Nb, 128>>>(A);
    for (int t = 0; t < Tt; t++) {
        int pi = t & 1;
        attn_xw_kernel<<<640, 256>>>(A, x, Wx, t, pi);
        step_kernel<<<dim3(16, 8), 256>>>(Wh, Wattn, b, out, t, pi);
    }
}

// round 12
// speedup vs baseline: 1.5158x; 1.0614x over previous
#include <cuda_runtime.h>
#include <cstdint>
#include <math.h>

#define Nb 512
#define Tt 64
#define Dd 512
#define Hh 512
#define FH 2048

// Persistent state (device globals: no allocations allowed)
__device__ float g_h[2][Nb * Hh];
__device__ float g_c[2][Nb * Hh];
__device__ float g_attn[Nb * Hh];
__device__ float g_xw[Nb * FH];   // x(t) @ Wx, natural FH column layout

#define ASTR 20
#define BSTR 136
#define A_FLOATS (64 * ASTR)
#define STAGE_FLOATS (64 * ASTR + 16 * BSTR)  // 3456 floats
#define NSTAGES 3

#define CP_ASYNC16(dst, src) \
    asm volatile("cp.async.cg.shared.global [%0], [%1], 16;\n" :: "r"(dst), "l"(src))
#define CP_COMMIT() asm volatile("cp.async.commit_group;\n")
#define CP_WAIT1()  asm volatile("cp.async.wait_group 1;\n")

__device__ __forceinline__ uint32_t smem_u32(const void* p) {
    return (uint32_t)__cvta_generic_to_shared(p);
}

// ---------------------------------------------------------------------------
// init: h0 = c0 = mean over the 16 spatial positions of A
// ---------------------------------------------------------------------------
__global__ __launch_bounds__(128) void init_kernel(const float* __restrict__ A) {
    int n = blockIdx.x, tid = threadIdx.x;
    const float4* base = (const float4*)(A + (size_t)n * Hh * 16);
#pragma unroll
    for (int i = 0; i < 4; i++) {
        int r = tid + i * 128;
        float4 v0 = base[r * 4 + 0], v1 = base[r * 4 + 1];
        float4 v2 = base[r * 4 + 2], v3 = base[r * 4 + 3];
        float s = (v0.x + v0.y + v0.z + v0.w) + (v1.x + v1.y + v1.z + v1.w)
                + (v2.x + v2.y + v2.z + v2.w) + (v3.x + v3.y + v3.z + v3.w);
        float m = s * (1.0f / 16.0f);
        g_h[0][n * Hh + r] = m;
        g_c[0][n * Hh + r] = m;
    }
}

// ---------------------------------------------------------------------------
// fused attn + xW kernel. 640 blocks x 256 threads.
//   blocks [0,128):   xW GEMM CTAs (LONG POLE -> launched first, occupy SMs
//                     immediately; round-4 proven mainloop, x/Wx, 32 iters)
//   blocks [128,640): attention for batch row n = blockIdx - 128 (light,
//                     backfills remaining slots and drains under xW)
// Both depend only on t-1 state / static inputs -> freely concurrent.
// ---------------------------------------------------------------------------
__global__ __launch_bounds__(256, 2) void attn_xw_kernel(
    const float* __restrict__ A, const float* __restrict__ x,
    const float* __restrict__ Wx, int t, int pi)
{
    __shared__ __align__(16) float sm[NSTAGES * STAGE_FLOATS];
    const int tid = threadIdx.x;

    if (blockIdx.x >= 128) {
        // ===================== attention path ===========================
        const int n = blockIdx.x - 128;
        const int lane = tid & 31, warp = tid >> 5;
        const float* hbuf = g_h[pi] + (size_t)n * Hh;
        const float4* base = (const float4*)(A + (size_t)n * Hh * 16);

        float (*red)[16] = (float(*)[16])sm;    // 8x16
        float* aw = sm + 128;                   // 16

        float4 av[2][4];
        float hv[2];
#pragma unroll
        for (int i = 0; i < 2; i++) {
            int r = tid + i * 256;
#pragma unroll
            for (int q = 0; q < 4; q++) av[i][q] = base[r * 4 + q];
            hv[i] = hbuf[r];
        }

        float Av[2][16];
#pragma unroll
        for (int i = 0; i < 2; i++)
#pragma unroll
            for (int q = 0; q < 4; q++) {
                Av[i][q * 4 + 0] = av[i][q].x; Av[i][q * 4 + 1] = av[i][q].y;
                Av[i][q * 4 + 2] = av[i][q].z; Av[i][q * 4 + 3] = av[i][q].w;
            }

        float part[16];
#pragma unroll
        for (int p = 0; p < 16; p++) part[p] = hv[0] * Av[0][p] + hv[1] * Av[1][p];

#pragma unroll
        for (int off = 16; off >= 1; off >>= 1)
#pragma unroll
            for (int p = 0; p < 16; p++)
                part[p] += __shfl_xor_sync(0xffffffffu, part[p], off);

        if (lane == 0) {
#pragma unroll
            for (int p = 0; p < 16; p++) red[warp][p] = part[p];
        }
        __syncthreads();

        if (warp == 0) {
            int p = lane & 15;
            const float scale = 0.044194173824159216f;  // 1/sqrt(512)
            float s = 0.f;
#pragma unroll
            for (int w8 = 0; w8 < 8; w8++) s += red[w8][p];
            s *= scale;
            float mx = s;
#pragma unroll
            for (int off = 8; off >= 1; off >>= 1)
                mx = fmaxf(mx, __shfl_xor_sync(0xffffffffu, mx, off));
            float e = expf(s - mx);
            float tot = e;
#pragma unroll
            for (int off = 8; off >= 1; off >>= 1)
                tot += __shfl_xor_sync(0xffffffffu, tot, off);
            if (lane < 16) aw[p] = e / tot;
        }
        __syncthreads();

        float wl[16];
#pragma unroll
        for (int p = 0; p < 16; p++) wl[p] = aw[p];
        float* ao = g_attn + (size_t)n * Hh;
#pragma unroll
        for (int i = 0; i < 2; i++) {
            float s = 0.f;
#pragma unroll
            for (int p = 0; p < 16; p++) s += Av[i][p] * wl[p];
            ao[tid + i * 256] = s;
        }
    } else {
        // ===================== xW GEMM path =============================
        const int b = blockIdx.x;
        const int j0 = (b & 15) * 32;
        const int n0 = (b >> 4) * 64;
        const float* xbase = x + (size_t)n0 * Tt * Dd + (size_t)t * Dd;
        const int am = tid >> 2, akq = (tid & 3) * 4;

        const int lane = tid & 31, wid = tid >> 5;
        const int wm = wid & 1, wn = wid >> 1;
        const int gid = lane >> 2, tg = lane & 3;

        float acc[2][4][4];
#pragma unroll
        for (int fm = 0; fm < 2; fm++)
#pragma unroll
            for (int fn = 0; fn < 4; fn++)
#pragma unroll
                for (int e = 0; e < 4; e++) acc[fm][fn][e] = 0.f;

        auto issue = [&](int i) {
            float* stg = sm + (i % NSTAGES) * STAGE_FLOATS;
            int kl = i << 4;
            const float* asrc = xbase + (size_t)am * (Tt * Dd) + kl + akq;
            CP_ASYNC16(smem_u32(stg + am * ASTR + akq), asrc);
            float* Bst = stg + A_FLOATS;
#pragma unroll
            for (int j = 0; j < 2; j++) {
                int e = tid + j * 256;
                int k = e >> 5, n4 = e & 31;
                const float* bsrc = Wx + (size_t)(kl + k) * FH + (n4 >> 3) * 512 + j0 + (n4 & 7) * 4;
                CP_ASYNC16(smem_u32(Bst + k * BSTR + n4 * 4), bsrc);
            }
        };

        issue(0); CP_COMMIT();
        issue(1); CP_COMMIT();

        for (int i = 0; i < 32; i++) {
            CP_WAIT1();
            __syncthreads();
            const float* As = sm + (i % NSTAGES) * STAGE_FLOATS;
            const float* Bs = As + A_FLOATS;
#pragma unroll
            for (int k8 = 0; k8 < 2; k8++) {
                int kb = k8 * 8;
                uint32_t a[2][4], bf[4][2];
#pragma unroll
                for (int fm = 0; fm < 2; fm++) {
                    int row = wm * 32 + fm * 16 + gid;
                    a[fm][0] = __float_as_uint(As[row * ASTR + kb + tg]);
                    a[fm][1] = __float_as_uint(As[(row + 8) * ASTR + kb + tg]);
                    a[fm][2] = __float_as_uint(As[row * ASTR + kb + tg + 4]);
                    a[fm][3] = __float_as_uint(As[(row + 8) * ASTR + kb + tg + 4]);
                }
#pragma unroll
                for (int fn = 0; fn < 4; fn++) {
                    int col = wn * 32 + fn * 8 + gid;
                    bf[fn][0] = __float_as_uint(Bs[(kb + tg) * BSTR + col]);
                    bf[fn][1] = __float_as_uint(Bs[(kb + tg + 4) * BSTR + col]);
                }
#pragma unroll
                for (int fm = 0; fm < 2; fm++)
#pragma unroll
                    for (int fn = 0; fn < 4; fn++) {
                        asm volatile(
                            "mma.sync.aligned.m16n8k8.row.col.f32.tf32.tf32.f32 "
                            "{%0,%1,%2,%3}, {%4,%5,%6,%7}, {%8,%9}, {%0,%1,%2,%3};\n"
                            : "+f"(acc[fm][fn][0]), "+f"(acc[fm][fn][1]),
                              "+f"(acc[fm][fn][2]), "+f"(acc[fm][fn][3])
                            : "r"(a[fm][0]), "r"(a[fm][1]), "r"(a[fm][2]), "r"(a[fm][3]),
                              "r"(bf[fn][0]), "r"(bf[fn][1]));
                    }
            }
            if (i + 2 < 32) issue(i + 2);
            CP_COMMIT();
        }

        // write raw tile to g_xw: col C -> fh col = wn*512 + j0 + fn*8 + tg*2
#pragma unroll
        for (int fm = 0; fm < 2; fm++)
#pragma unroll
            for (int fn = 0; fn < 4; fn++) {
                int R = wm * 32 + fm * 16 + gid;
                int fc = wn * 512 + j0 + fn * 8 + tg * 2;
                *(float2*)&g_xw[(size_t)(n0 + R) * FH + fc] =
                    make_float2(acc[fm][fn][0], acc[fm][fn][1]);
                *(float2*)&g_xw[(size_t)(n0 + R + 8) * FH + fc] =
                    make_float2(acc[fm][fn][2], acc[fm][fn][3]);
            }
    }
}

// ---------------------------------------------------------------------------
// sequential step: K=1024 (h-seg + attn-seg), acc initialized from g_xw,
// round-4 proven mainloop + gate epilogue. Grid (16,8), 256 threads.
// ---------------------------------------------------------------------------
__global__ __launch_bounds__(256, 1) void step_kernel(
    const float* __restrict__ Wh, const float* __restrict__ Wattn,
    const float* __restrict__ bias, float* __restrict__ out, int t, int pi)
{
    __shared__ __align__(16) float sm[NSTAGES * STAGE_FLOATS];
    const int tid = threadIdx.x;
    const int j0 = blockIdx.x * 32;
    const int n0 = blockIdx.y * 64;
    const float* h_in = g_h[pi];
    const float* c_in = g_c[pi];
    float* h_out = g_h[pi ^ 1];
    float* c_out = g_c[pi ^ 1];

    const int am = tid >> 2, akq = (tid & 3) * 4;
    const int lane = tid & 31, wid = tid >> 5;
    const int wm = wid & 1, wn = wid >> 1;
    const int gid = lane >> 2, tg = lane & 3;

    // acc init from g_xw (each thread loads its owned elements)
    float acc[2][4][4];
#pragma unroll
    for (int fm = 0; fm < 2; fm++)
#pragma unroll
        for (int fn = 0; fn < 4; fn++) {
            int R = wm * 32 + fm * 16 + gid;
            int fc = wn * 512 + j0 + fn * 8 + tg * 2;
            float2 v0 = *(const float2*)&g_xw[(size_t)(n0 + R) * FH + fc];
            float2 v1 = *(const float2*)&g_xw[(size_t)(n0 + R + 8) * FH + fc];
            acc[fm][fn][0] = v0.x; acc[fm][fn][1] = v0.y;
            acc[fm][fn][2] = v1.x; acc[fm][fn][3] = v1.y;
        }

    auto issue = [&](int i) {
        float* stg = sm + (i % NSTAGES) * STAGE_FLOATS;
        int seg = i >> 5;
        int kl = (i & 31) << 4;
        const float* Ab; const float* W;
        if (seg == 0) { Ab = h_in   + (size_t)n0 * Hh; W = Wh; }
        else          { Ab = g_attn + (size_t)n0 * Hh; W = Wattn; }
        const float* asrc = Ab + (size_t)am * Hh + kl + akq;
        CP_ASYNC16(smem_u32(stg + am * ASTR + akq), asrc);
        float* Bst = stg + A_FLOATS;
#pragma unroll
        for (int j = 0; j < 2; j++) {
            int e = tid + j * 256;
            int k = e >> 5, n4 = e & 31;
            const float* bsrc = W + (size_t)(kl + k) * FH + (n4 >> 3) * 512 + j0 + (n4 & 7) * 4;
            CP_ASYNC16(smem_u32(Bst + k * BSTR + n4 * 4), bsrc);
        }
    };

    issue(0); CP_COMMIT();
    issue(1); CP_COMMIT();

    for (int i = 0; i < 64; i++) {
        CP_WAIT1();
        __syncthreads();
        const float* As = sm + (i % NSTAGES) * STAGE_FLOATS;
        const float* Bs = As + A_FLOATS;
#pragma unroll
        for (int k8 = 0; k8 < 2; k8++) {
            int kb = k8 * 8;
            uint32_t a[2][4], bf[4][2];
#pragma unroll
            for (int fm = 0; fm < 2; fm++) {
                int row = wm * 32 + fm * 16 + gid;
                a[fm][0] = __float_as_uint(As[row * ASTR + kb + tg]);
                a[fm][1] = __float_as_uint(As[(row + 8) * ASTR + kb + tg]);
                a[fm][2] = __float_as_uint(As[row * ASTR + kb + tg + 4]);
                a[fm][3] = __float_as_uint(As[(row + 8) * ASTR + kb + tg + 4]);
            }
#pragma unroll
            for (int fn = 0; fn < 4; fn++) {
                int col = wn * 32 + fn * 8 + gid;
                bf[fn][0] = __float_as_uint(Bs[(kb + tg) * BSTR + col]);
                bf[fn][1] = __float_as_uint(Bs[(kb + tg + 4) * BSTR + col]);
            }
#pragma unroll
            for (int fm = 0; fm < 2; fm++)
#pragma unroll
                for (int fn = 0; fn < 4; fn++) {
                    asm volatile(
                        "mma.sync.aligned.m16n8k8.row.col.f32.tf32.tf32.f32 "
                        "{%0,%1,%2,%3}, {%4,%5,%6,%7}, {%8,%9}, {%0,%1,%2,%3};\n"
                        : "+f"(acc[fm][fn][0]), "+f"(acc[fm][fn][1]),
                          "+f"(acc[fm][fn][2]), "+f"(acc[fm][fn][3])
                        : "r"(a[fm][0]), "r"(a[fm][1]), "r"(a[fm][2]), "r"(a[fm][3]),
                          "r"(bf[fn][0]), "r"(bf[fn][1]));
                }
        }
        if (i + 2 < 64) issue(i + 2);
        CP_COMMIT();
    }

    __syncthreads();
    // stash a-tile (64 x 128) in smem for gate gathering
    float (*atile)[132] = (float(*)[132])sm;
#pragma unroll
    for (int fm = 0; fm < 2; fm++)
#pragma unroll
        for (int fn = 0; fn < 4; fn++) {
            int R = wm * 32 + fm * 16 + gid, C = wn * 32 + fn * 8 + tg * 2;
            atile[R][C]         = acc[fm][fn][0];
            atile[R][C + 1]     = acc[fm][fn][1];
            atile[R + 8][C]     = acc[fm][fn][2];
            atile[R + 8][C + 1] = acc[fm][fn][3];
        }
    __syncthreads();

    {
        int col = tid & 31;
        int r0 = tid >> 5;
        float bi = bias[j0 + col];
        float bff = bias[512 + j0 + col];
        float bo = bias[1024 + j0 + col];
        float bg = bias[1536 + j0 + col];
#pragma unroll
        for (int q = 0; q < 8; q++) {
            int row = r0 + q * 8;
            float vi = atile[row][col]      + bi;
            float vf = atile[row][col + 32] + bff;
            float vo = atile[row][col + 64] + bo;
            float vg = atile[row][col + 96] + bg;
            float ig = 1.f / (1.f + expf(-vi));
            float fg = 1.f / (1.f + expf(-vf));
            float og = 1.f / (1.f + expf(-vo));
            float gg = tanhf(vg);
            int n = n0 + row, hc = j0 + col;
            float cold = c_in[n * Hh + hc];
            float cn = fg * cold + ig * gg;
            float hn = og * tanhf(cn);
            c_out[n * Hh + hc] = cn;
            h_out[n * Hh + hc] = hn;
            out[((size_t)n * Tt + t) * Hh + hc] = hn;
        }
    }
}

// ---------------------------------------------------------------------------
extern "C" void kernel_launch(void* const* d_in, const int* in_sizes, int n_in,
                              void* d_out, int out_size) {
    const float* x     = (const float*)d_in[0];
    const float* A     = (const float*)d_in[1];
    const float* Wx    = (const float*)d_in[2];
    const float* Wh    = (const float*)d_in[3];
    const float* Wattn = (const float*)d_in[4];
    const float* b     = (const float*)d_in[5];
    float* out = (float*)d_out;

    init_kernel<<<Nb, 128>>>(A);
    for (int t = 0; t < Tt; t++) {
        int pi = t & 1;
        attn_xw_kernel<<<640, 256>>>(A, x, Wx, t, pi);
        step_kernel<<<dim3(16, 8), 256>>>(Wh, Wattn, b, out, t, pi);
    }
}

// round 13
// speedup vs baseline: 1.7710x; 1.1683x over previous
#include <cuda_runtime.h>
#include <cstdint>
#include <math.h>

#define Nb 512
#define Tt 64
#define Dd 512
#define Hh 512
#define FH 2048

// Persistent state (device globals: no allocations allowed)
__device__ float g_h[2][Nb * Hh];
__device__ float g_c[2][Nb * Hh];
__device__ float g_attn[Nb * Hh];
__device__ float g_xw[(size_t)Nb * Tt * FH];  // x @ Wx for ALL timesteps, row m = n*Tt + t

#define ASTR 20
#define BSTR 136
#define A_FLOATS (64 * ASTR)
#define STAGE_FLOATS (64 * ASTR + 16 * BSTR)  // 3456 floats
#define NSTAGES 3

#define CP_ASYNC16(dst, src) \
    asm volatile("cp.async.cg.shared.global [%0], [%1], 16;\n" :: "r"(dst), "l"(src))
#define CP_COMMIT() asm volatile("cp.async.commit_group;\n")
#define CP_WAIT1()  asm volatile("cp.async.wait_group 1;\n")

__device__ __forceinline__ uint32_t smem_u32(const void* p) {
    return (uint32_t)__cvta_generic_to_shared(p);
}

// ---------------------------------------------------------------------------
// init: h0 = c0 = mean over the 16 spatial positions of A
// ---------------------------------------------------------------------------
__global__ __launch_bounds__(128) void init_kernel(const float* __restrict__ A) {
    int n = blockIdx.x, tid = threadIdx.x;
    const float4* base = (const float4*)(A + (size_t)n * Hh * 16);
#pragma unroll
    for (int i = 0; i < 4; i++) {
        int r = tid + i * 128;
        float4 v0 = base[r * 4 + 0], v1 = base[r * 4 + 1];
        float4 v2 = base[r * 4 + 2], v3 = base[r * 4 + 3];
        float s = (v0.x + v0.y + v0.z + v0.w) + (v1.x + v1.y + v1.z + v1.w)
                + (v2.x + v2.y + v2.z + v2.w) + (v3.x + v3.y + v3.z + v3.w);
        float m = s * (1.0f / 16.0f);
        g_h[0][n * Hh + r] = m;
        g_c[0][n * Hh + r] = m;
    }
}

// ---------------------------------------------------------------------------
// ONE-TIME big GEMM: g_xw = x @ Wx for all (n,t) rows. M = Nb*Tt = 32768.
// Grid (16, 512) = 8192 CTAs; proven round-4 CTA body, 32 K-iters, 2 CTAs/SM.
// x is (N,T,D) contiguous, so GEMM row m = n*Tt + t is just x + m*Dd.
// ---------------------------------------------------------------------------
__global__ __launch_bounds__(256, 2) void xw_all_kernel(
    const float* __restrict__ x, const float* __restrict__ Wx)
{
    __shared__ __align__(16) float sm[NSTAGES * STAGE_FLOATS];
    const int tid = threadIdx.x;
    const int j0 = blockIdx.x * 32;
    const int m0 = blockIdx.y * 64;          // row tile over m = n*Tt + t
    const float* xbase = x + (size_t)m0 * Dd;
    const int am = tid >> 2, akq = (tid & 3) * 4;

    const int lane = tid & 31, wid = tid >> 5;
    const int wm = wid & 1, wn = wid >> 1;
    const int gid = lane >> 2, tg = lane & 3;

    float acc[2][4][4];
#pragma unroll
    for (int fm = 0; fm < 2; fm++)
#pragma unroll
        for (int fn = 0; fn < 4; fn++)
#pragma unroll
            for (int e = 0; e < 4; e++) acc[fm][fn][e] = 0.f;

    auto issue = [&](int i) {
        float* stg = sm + (i % NSTAGES) * STAGE_FLOATS;
        int kl = i << 4;
        const float* asrc = xbase + (size_t)am * Dd + kl + akq;
        CP_ASYNC16(smem_u32(stg + am * ASTR + akq), asrc);
        float* Bst = stg + A_FLOATS;
#pragma unroll
        for (int j = 0; j < 2; j++) {
            int e = tid + j * 256;
            int k = e >> 5, n4 = e & 31;
            const float* bsrc = Wx + (size_t)(kl + k) * FH + (n4 >> 3) * 512 + j0 + (n4 & 7) * 4;
            CP_ASYNC16(smem_u32(Bst + k * BSTR + n4 * 4), bsrc);
        }
    };

    issue(0); CP_COMMIT();
    issue(1); CP_COMMIT();

    for (int i = 0; i < 32; i++) {
        CP_WAIT1();
        __syncthreads();
        const float* As = sm + (i % NSTAGES) * STAGE_FLOATS;
        const float* Bs = As + A_FLOATS;
#pragma unroll
        for (int k8 = 0; k8 < 2; k8++) {
            int kb = k8 * 8;
            uint32_t a[2][4], bf[4][2];
#pragma unroll
            for (int fm = 0; fm < 2; fm++) {
                int row = wm * 32 + fm * 16 + gid;
                a[fm][0] = __float_as_uint(As[row * ASTR + kb + tg]);
                a[fm][1] = __float_as_uint(As[(row + 8) * ASTR + kb + tg]);
                a[fm][2] = __float_as_uint(As[row * ASTR + kb + tg + 4]);
                a[fm][3] = __float_as_uint(As[(row + 8) * ASTR + kb + tg + 4]);
            }
#pragma unroll
            for (int fn = 0; fn < 4; fn++) {
                int col = wn * 32 + fn * 8 + gid;
                bf[fn][0] = __float_as_uint(Bs[(kb + tg) * BSTR + col]);
                bf[fn][1] = __float_as_uint(Bs[(kb + tg + 4) * BSTR + col]);
            }
#pragma unroll
            for (int fm = 0; fm < 2; fm++)
#pragma unroll
                for (int fn = 0; fn < 4; fn++) {
                    asm volatile(
                        "mma.sync.aligned.m16n8k8.row.col.f32.tf32.tf32.f32 "
                        "{%0,%1,%2,%3}, {%4,%5,%6,%7}, {%8,%9}, {%0,%1,%2,%3};\n"
                        : "+f"(acc[fm][fn][0]), "+f"(acc[fm][fn][1]),
                          "+f"(acc[fm][fn][2]), "+f"(acc[fm][fn][3])
                        : "r"(a[fm][0]), "r"(a[fm][1]), "r"(a[fm][2]), "r"(a[fm][3]),
                          "r"(bf[fn][0]), "r"(bf[fn][1]));
                }
        }
        if (i + 2 < 32) issue(i + 2);
        CP_COMMIT();
    }

    // write raw tile: col C -> fh col = wn*512 + j0 + fn*8 + tg*2
#pragma unroll
    for (int fm = 0; fm < 2; fm++)
#pragma unroll
        for (int fn = 0; fn < 4; fn++) {
            int R = wm * 32 + fm * 16 + gid;
            int fc = wn * 512 + j0 + fn * 8 + tg * 2;
            *(float2*)&g_xw[(size_t)(m0 + R) * FH + fc] =
                make_float2(acc[fm][fn][0], acc[fm][fn][1]);
            *(float2*)&g_xw[(size_t)(m0 + R + 8) * FH + fc] =
                make_float2(acc[fm][fn][2], acc[fm][fn][3]);
        }
}

// ---------------------------------------------------------------------------
// attention (proven round-4 version): one block per batch row, 128 threads,
// A row in registers, read once.
// ---------------------------------------------------------------------------
__global__ __launch_bounds__(128) void attn_kernel(const float* __restrict__ A, int pi) {
    int n = blockIdx.x, tid = threadIdx.x;
    int lane = tid & 31, warp = tid >> 5;
    const float* hbuf = g_h[pi] + (size_t)n * Hh;
    const float4* base = (const float4*)(A + (size_t)n * Hh * 16);

    float Av[4][16];
    float hv[4];
    float part[16];
#pragma unroll
    for (int p = 0; p < 16; p++) part[p] = 0.f;

#pragma unroll
    for (int i = 0; i < 4; i++) {
        int r = tid + i * 128;
#pragma unroll
        for (int q = 0; q < 4; q++) {
            float4 v = base[r * 4 + q];
            Av[i][q * 4 + 0] = v.x; Av[i][q * 4 + 1] = v.y;
            Av[i][q * 4 + 2] = v.z; Av[i][q * 4 + 3] = v.w;
        }
        hv[i] = hbuf[r];
#pragma unroll
        for (int p = 0; p < 16; p++) part[p] += hv[i] * Av[i][p];
    }

#pragma unroll
    for (int off = 16; off >= 1; off >>= 1)
#pragma unroll
        for (int p = 0; p < 16; p++)
            part[p] += __shfl_xor_sync(0xffffffffu, part[p], off);

    __shared__ float red[4][16];
    __shared__ float w[16];
    if (lane == 0) {
#pragma unroll
        for (int p = 0; p < 16; p++) red[warp][p] = part[p];
    }
    __syncthreads();
    if (tid == 0) {
        const float scale = 0.044194173824159216f;  // 1/sqrt(512)
        float sc[16];
        float mx = -1e30f;
#pragma unroll
        for (int p = 0; p < 16; p++) {
            sc[p] = (red[0][p] + red[1][p] + red[2][p] + red[3][p]) * scale;
            mx = fmaxf(mx, sc[p]);
        }
        float s = 0.f;
#pragma unroll
        for (int p = 0; p < 16; p++) { float e = expf(sc[p] - mx); w[p] = e; s += e; }
        float inv = 1.f / s;
#pragma unroll
        for (int p = 0; p < 16; p++) w[p] *= inv;
    }
    __syncthreads();

    float wl[16];
#pragma unroll
    for (int p = 0; p < 16; p++) wl[p] = w[p];
    float* ao = g_attn + (size_t)n * Hh;
#pragma unroll
    for (int i = 0; i < 4; i++) {
        float s = 0.f;
#pragma unroll
        for (int p = 0; p < 16; p++) s += Av[i][p] * wl[p];
        ao[tid + i * 128] = s;
    }
}

// ---------------------------------------------------------------------------
// sequential step: K=1024 (h-seg + attn-seg), acc initialized from g_xw
// (row n*Tt + t), round-4 proven mainloop + gate epilogue.
// ---------------------------------------------------------------------------
__global__ __launch_bounds__(256, 1) void step_kernel(
    const float* __restrict__ Wh, const float* __restrict__ Wattn,
    const float* __restrict__ bias, float* __restrict__ out, int t, int pi)
{
    __shared__ __align__(16) float sm[NSTAGES * STAGE_FLOATS];
    const int tid = threadIdx.x;
    const int j0 = blockIdx.x * 32;
    const int n0 = blockIdx.y * 64;
    const float* h_in = g_h[pi];
    const float* c_in = g_c[pi];
    float* h_out = g_h[pi ^ 1];
    float* c_out = g_c[pi ^ 1];

    const int am = tid >> 2, akq = (tid & 3) * 4;
    const int lane = tid & 31, wid = tid >> 5;
    const int wm = wid & 1, wn = wid >> 1;
    const int gid = lane >> 2, tg = lane & 3;

    // acc init from g_xw (row m = n*Tt + t)
    float acc[2][4][4];
#pragma unroll
    for (int fm = 0; fm < 2; fm++)
#pragma unroll
        for (int fn = 0; fn < 4; fn++) {
            int R = wm * 32 + fm * 16 + gid;
            int fc = wn * 512 + j0 + fn * 8 + tg * 2;
            float2 v0 = *(const float2*)&g_xw[((size_t)(n0 + R) * Tt + t) * FH + fc];
            float2 v1 = *(const float2*)&g_xw[((size_t)(n0 + R + 8) * Tt + t) * FH + fc];
            acc[fm][fn][0] = v0.x; acc[fm][fn][1] = v0.y;
            acc[fm][fn][2] = v1.x; acc[fm][fn][3] = v1.y;
        }

    auto issue = [&](int i) {
        float* stg = sm + (i % NSTAGES) * STAGE_FLOATS;
        int seg = i >> 5;
        int kl = (i & 31) << 4;
        const float* Ab; const float* W;
        if (seg == 0) { Ab = h_in   + (size_t)n0 * Hh; W = Wh; }
        else          { Ab = g_attn + (size_t)n0 * Hh; W = Wattn; }
        const float* asrc = Ab + (size_t)am * Hh + kl + akq;
        CP_ASYNC16(smem_u32(stg + am * ASTR + akq), asrc);
        float* Bst = stg + A_FLOATS;
#pragma unroll
        for (int j = 0; j < 2; j++) {
            int e = tid + j * 256;
            int k = e >> 5, n4 = e & 31;
            const float* bsrc = W + (size_t)(kl + k) * FH + (n4 >> 3) * 512 + j0 + (n4 & 7) * 4;
            CP_ASYNC16(smem_u32(Bst + k * BSTR + n4 * 4), bsrc);
        }
    };

    issue(0); CP_COMMIT();
    issue(1); CP_COMMIT();

    for (int i = 0; i < 64; i++) {
        CP_WAIT1();
        __syncthreads();
        const float* As = sm + (i % NSTAGES) * STAGE_FLOATS;
        const float* Bs = As + A_FLOATS;
#pragma unroll
        for (int k8 = 0; k8 < 2; k8++) {
            int kb = k8 * 8;
            uint32_t a[2][4], bf[4][2];
#pragma unroll
            for (int fm = 0; fm < 2; fm++) {
                int row = wm * 32 + fm * 16 + gid;
                a[fm][0] = __float_as_uint(As[row * ASTR + kb + tg]);
                a[fm][1] = __float_as_uint(As[(row + 8) * ASTR + kb + tg]);
                a[fm][2] = __float_as_uint(As[row * ASTR + kb + tg + 4]);
                a[fm][3] = __float_as_uint(As[(row + 8) * ASTR + kb + tg + 4]);
            }
#pragma unroll
            for (int fn = 0; fn < 4; fn++) {
                int col = wn * 32 + fn * 8 + gid;
                bf[fn][0] = __float_as_uint(Bs[(kb + tg) * BSTR + col]);
                bf[fn][1] = __float_as_uint(Bs[(kb + tg + 4) * BSTR + col]);
            }
#pragma unroll
            for (int fm = 0; fm < 2; fm++)
#pragma unroll
                for (int fn = 0; fn < 4; fn++) {
                    asm volatile(
                        "mma.sync.aligned.m16n8k8.row.col.f32.tf32.tf32.f32 "
                        "{%0,%1,%2,%3}, {%4,%5,%6,%7}, {%8,%9}, {%0,%1,%2,%3};\n"
                        : "+f"(acc[fm][fn][0]), "+f"(acc[fm][fn][1]),
                          "+f"(acc[fm][fn][2]), "+f"(acc[fm][fn][3])
                        : "r"(a[fm][0]), "r"(a[fm][1]), "r"(a[fm][2]), "r"(a[fm][3]),
                          "r"(bf[fn][0]), "r"(bf[fn][1]));
                }
        }
        if (i + 2 < 64) issue(i + 2);
        CP_COMMIT();
    }

    __syncthreads();
    // stash a-tile (64 x 128) in smem for gate gathering
    float (*atile)[132] = (float(*)[132])sm;
#pragma unroll
    for (int fm = 0; fm < 2; fm++)
#pragma unroll
        for (int fn = 0; fn < 4; fn++) {
            int R = wm * 32 + fm * 16 + gid, C = wn * 32 + fn * 8 + tg * 2;
            atile[R][C]         = acc[fm][fn][0];
            atile[R][C + 1]     = acc[fm][fn][1];
            atile[R + 8][C]     = acc[fm][fn][2];
            atile[R + 8][C + 1] = acc[fm][fn][3];
        }
    __syncthreads();

    {
        int col = tid & 31;
        int r0 = tid >> 5;
        float bi = bias[j0 + col];
        float bff = bias[512 + j0 + col];
        float bo = bias[1024 + j0 + col];
        float bg = bias[1536 + j0 + col];
#pragma unroll
        for (int q = 0; q < 8; q++) {
            int row = r0 + q * 8;
            float vi = atile[row][col]      + bi;
            float vf = atile[row][col + 32] + bff;
            float vo = atile[row][col + 64] + bo;
            float vg = atile[row][col + 96] + bg;
            float ig = 1.f / (1.f + expf(-vi));
            float fg = 1.f / (1.f + expf(-vf));
            float og = 1.f / (1.f + expf(-vo));
            float gg = tanhf(vg);
            int n = n0 + row, hc = j0 + col;
            float cold = c_in[n * Hh + hc];
            float cn = fg * cold + ig * gg;
            float hn = og * tanhf(cn);
            c_out[n * Hh + hc] = cn;
            h_out[n * Hh + hc] = hn;
            out[((size_t)n * Tt + t) * Hh + hc] = hn;
        }
    }
}

// ---------------------------------------------------------------------------
extern "C" void kernel_launch(void* const* d_in, const int* in_sizes, int n_in,
                              void* d_out, int out_size) {
    const float* x     = (const float*)d_in[0];
    const float* A     = (const float*)d_in[1];
    const float* Wx    = (const float*)d_in[2];
    const float* Wh    = (const float*)d_in[3];
    const float* Wattn = (const float*)d_in[4];
    const float* b     = (const float*)d_in[5];
    float* out = (float*)d_out;

    xw_all_kernel<<<dim3(16, 512), 256>>>(x, Wx);   // no deps; runs while init finishes
    init_kernel<<<Nb, 128>>>(A);
    for (int t = 0; t < Tt; t++) {
        int pi = t & 1;
        attn_kernel<<<Nb, 128>>>(A, pi);
        step_kernel<<<dim3(16, 8), 256>>>(Wh, Wattn, b, out, t, pi);
    }
}